// round 2
// baseline (speedup 1.0000x reference)
#include <cuda_runtime.h>
#include <cstdint>

#define TT 1024
#define RR 64
#define SS 16
#define MMEM 16
#define BB 8
#define DD 512
#define HH 8
#define DHH 64
#define TQ_ 1104
#define TK_ 1104
#define SCALE_ 0.125f
#define NEGINF_ (-1.0e8f)

// scratch (allocation-free rule: device globals)
__device__ float g_query[(size_t)TQ_ * BB * DD];
__device__ float g_key  [(size_t)TK_ * BB * DD];
__device__ float g_value[(size_t)TK_ * BB * DD];
__device__ float g_attn [(size_t)TQ_ * BB * DD];
__device__ unsigned char g_mask[(size_t)TQ_ * TK_];
__device__ int g_mask_mode;

__device__ __forceinline__ float neg_inf_f() { return __int_as_float(0xff800000); }

// ---------------------------------------------------------------------------
// Mask dtype detection + canonicalization.
// The attention_mask is bool in the reference; the harness may materialize it
// as uint8 (1B), int32 (4B) or float32 (4B). Sample the first 256KB (safe:
// buffer is >= elem_count bytes under every candidate dtype) and classify:
//   any byte > 1                      -> float32 (bytes 0x80 / 0x3F of 1.0f)
//   all bytes at off%4 != 0 are zero  -> int32   ([v,0,0,0] groups)
//   otherwise                         -> uint8
// ---------------------------------------------------------------------------
__global__ void detect_mask_mode_kernel(const unsigned char* __restrict__ buf)
{
    __shared__ int s_large, s_nzoff;
    if (threadIdx.x == 0) { s_large = 0; s_nzoff = 0; }
    __syncthreads();
    const int N = 1 << 18;  // 256KB sample < TQ_*TK_ bytes
    int l = 0, z = 0;
    for (int i = threadIdx.x; i < N; i += blockDim.x) {
        unsigned char v = buf[i];
        if (v > 1) l = 1;
        if ((i & 3) && v != 0) z = 1;
    }
    if (l) atomicOr(&s_large, 1);
    if (z) atomicOr(&s_nzoff, 1);
    __syncthreads();
    if (threadIdx.x == 0)
        g_mask_mode = s_large ? 2 : (s_nzoff ? 0 : 1);  // 0=u8, 1=i32, 2=f32
}

__global__ void convert_mask_kernel(const unsigned char* __restrict__ buf)
{
    const int idx = blockIdx.x * blockDim.x + threadIdx.x;
    if (idx >= TQ_ * TK_) return;
    const int mode = g_mask_mode;
    unsigned char m;
    if (mode == 0)      m = buf[idx] ? 1 : 0;
    else if (mode == 1) m = (((const int*)buf)[idx] != 0) ? 1 : 0;
    else                m = (((const float*)buf)[idx] != 0.f) ? 1 : 0;
    g_mask[idx] = m;
}

// ---------------------------------------------------------------------------
// GEMM: out[m, n] = gather_A(m) dot W[n, :] + bias[n]   (W row-major N x K)
// MODE 0: A = q_in (rc | utt | sum) -> g_query, scaled by SCALE_
// MODE 1: A = kv_in (mem | rc | utt) -> g_key / g_value split at n=512
// MODE 2: A = g_attn -> d_out with right_context / clipped mems split
// BM=BN=128, BK=8, 256 threads, 8x8 microtile.
// ---------------------------------------------------------------------------
template <int MODE>
__global__ void __launch_bounds__(256) gemm_kernel(
    const float* __restrict__ utt, const float* __restrict__ rc,
    const float* __restrict__ smr, const float* __restrict__ mem,
    const float* __restrict__ W, const float* __restrict__ bias,
    float* __restrict__ dout)
{
    __shared__ float As[8][128];
    __shared__ float Bs[8][128];

    const int tid  = threadIdx.x;
    const int m0   = blockIdx.y * 128;
    const int n0   = blockIdx.x * 128;
    const int lm   = tid >> 1;
    const int half = tid & 1;

    const int row = m0 + lm;
    const int t   = row >> 3;
    const int bb  = row & 7;
    const float* arow;
    if (MODE == 0) {
        if (t < RR)           arow = rc  + ((size_t)t * BB + bb) * DD;
        else if (t < RR + TT) arow = utt + ((size_t)(t - RR) * BB + bb) * DD;
        else                  arow = smr + ((size_t)(t - RR - TT) * BB + bb) * DD;
    } else if (MODE == 1) {
        if (t < MMEM)             arow = mem + ((size_t)t * BB + bb) * DD;
        else if (t < MMEM + RR)   arow = rc  + ((size_t)(t - MMEM) * BB + bb) * DD;
        else                      arow = utt + ((size_t)(t - MMEM - RR) * BB + bb) * DD;
    } else {
        arow = g_attn + (size_t)row * DD;
    }
    const float* brow = W + (size_t)(n0 + lm) * DD;

    const int ty = tid >> 4;
    const int tx = tid & 15;

    float acc[8][8];
#pragma unroll
    for (int i = 0; i < 8; i++)
#pragma unroll
        for (int j = 0; j < 8; j++) acc[i][j] = 0.f;

    for (int k0 = 0; k0 < DD; k0 += 8) {
        float4 av = *(const float4*)(arow + k0 + half * 4);
        float4 bv = *(const float4*)(brow + k0 + half * 4);
        __syncthreads();
        As[half * 4 + 0][lm] = av.x; As[half * 4 + 1][lm] = av.y;
        As[half * 4 + 2][lm] = av.z; As[half * 4 + 3][lm] = av.w;
        Bs[half * 4 + 0][lm] = bv.x; Bs[half * 4 + 1][lm] = bv.y;
        Bs[half * 4 + 2][lm] = bv.z; Bs[half * 4 + 3][lm] = bv.w;
        __syncthreads();
#pragma unroll
        for (int kk = 0; kk < 8; kk++) {
            float4 a0 = *(const float4*)&As[kk][ty * 8];
            float4 a1 = *(const float4*)&As[kk][ty * 8 + 4];
            float4 b0 = *(const float4*)&Bs[kk][tx * 8];
            float4 b1 = *(const float4*)&Bs[kk][tx * 8 + 4];
            float ar[8] = {a0.x, a0.y, a0.z, a0.w, a1.x, a1.y, a1.z, a1.w};
            float br[8] = {b0.x, b0.y, b0.z, b0.w, b1.x, b1.y, b1.z, b1.w};
#pragma unroll
            for (int i = 0; i < 8; i++)
#pragma unroll
                for (int j = 0; j < 8; j++)
                    acc[i][j] += ar[i] * br[j];
        }
    }

#pragma unroll
    for (int i = 0; i < 8; i++) {
        const int r  = m0 + ty * 8 + i;
        const int tt = r >> 3;
        const int rb = r & 7;
#pragma unroll
        for (int j = 0; j < 8; j++) {
            const int n = n0 + tx * 8 + j;
            float v = acc[i][j] + bias[n];
            if (MODE == 0) {
                g_query[(size_t)r * DD + n] = v * SCALE_;
            } else if (MODE == 1) {
                if (n < DD) g_key  [(size_t)r * DD + n]        = v;
                else        g_value[(size_t)r * DD + (n - DD)] = v;
            } else {
                if (tt < TQ_ - SS) {
                    dout[(size_t)r * DD + n] = v;
                } else if (tt < TQ_ - 1) {
                    v = fminf(10.f, fmaxf(-10.f, v));
                    dout[(size_t)(TQ_ - SS) * BB * DD +
                         ((size_t)(tt - (TQ_ - SS)) * BB + rb) * DD + n] = v;
                }
                // tt == TQ_-1 dropped by reference ([:-1])
            }
        }
    }
}

// ---------------------------------------------------------------------------
// Flash attention: per (q-tile of 64, b, h). 256 threads as 16x16, each thread
// owns a 4(q) x 4(k or dh) microtile. Online softmax with shuffle reductions
// across the 16 lanes sharing a q row.
// ---------------------------------------------------------------------------
__global__ void __launch_bounds__(256) attn_kernel(const int* __restrict__ lengths)
{
    extern __shared__ float sh[];
    float* Qt = sh;                       // Qt[d*64 + q]
    float* KP = sh + 64 * 64;             // Kt[d*65 + k]  /  P^T[k*65 + q]
    float* Vs = sh + 64 * 64 + 64 * 65;   // Vs[k*64 + d]

    const int tid = threadIdx.x;
    const int ty  = tid >> 4;
    const int tx  = tid & 15;
    const int bh  = blockIdx.y;
    const int b   = bh >> 3;
    const int h   = bh & 7;
    const int q0  = blockIdx.x * 64;

    int maxlen = 0;
#pragma unroll
    for (int i = 0; i < BB; i++) maxlen = max(maxlen, lengths[i]);
    const int klen = lengths[b] + MMEM + (TQ_ - maxlen - SS);

    // load Q tile (transposed, once per block)
#pragma unroll
    for (int it = 0; it < 4; it++) {
        int idx = it * 256 + tid;
        int q   = idx >> 4;
        int d   = (idx & 15) * 4;
        float4 v = make_float4(0.f, 0.f, 0.f, 0.f);
        int t = q0 + q;
        if (t < TQ_)
            v = *(const float4*)&g_query[((size_t)t * BB + b) * DD + h * DHH + d];
        Qt[(d + 0) * 64 + q] = v.x;
        Qt[(d + 1) * 64 + q] = v.y;
        Qt[(d + 2) * 64 + q] = v.z;
        Qt[(d + 3) * 64 + q] = v.w;
    }

    float mrow[4], lrow[4], o[4][4];
#pragma unroll
    for (int i = 0; i < 4; i++) {
        mrow[i] = neg_inf_f();
        lrow[i] = 0.f;
#pragma unroll
        for (int j = 0; j < 4; j++) o[i][j] = 0.f;
    }

    for (int k0 = 0; k0 < TK_; k0 += 64) {
        __syncthreads();  // previous PV done reading KP/Vs
#pragma unroll
        for (int it = 0; it < 4; it++) {
            int idx = it * 256 + tid;
            int k   = idx >> 4;
            int d   = (idx & 15) * 4;
            int tk  = k0 + k;
            float4 kv = make_float4(0.f, 0.f, 0.f, 0.f);
            float4 vv = make_float4(0.f, 0.f, 0.f, 0.f);
            if (tk < TK_) {
                kv = *(const float4*)&g_key  [((size_t)tk * BB + b) * DD + h * DHH + d];
                vv = *(const float4*)&g_value[((size_t)tk * BB + b) * DD + h * DHH + d];
            }
            KP[(d + 0) * 65 + k] = kv.x;
            KP[(d + 1) * 65 + k] = kv.y;
            KP[(d + 2) * 65 + k] = kv.z;
            KP[(d + 3) * 65 + k] = kv.w;
            *(float4*)&Vs[k * 64 + d] = vv;
        }
        __syncthreads();

        // scores s[4q][4k] = Q . K^T  (SCALE folded into g_query)
        float s[4][4];
#pragma unroll
        for (int i = 0; i < 4; i++)
#pragma unroll
            for (int j = 0; j < 4; j++) s[i][j] = 0.f;

#pragma unroll 16
        for (int d = 0; d < 64; d++) {
            float a0 = Qt[d * 64 + ty * 4 + 0];
            float a1 = Qt[d * 64 + ty * 4 + 1];
            float a2 = Qt[d * 64 + ty * 4 + 2];
            float a3 = Qt[d * 64 + ty * 4 + 3];
            float c0 = KP[d * 65 + tx * 4 + 0];
            float c1 = KP[d * 65 + tx * 4 + 1];
            float c2 = KP[d * 65 + tx * 4 + 2];
            float c3 = KP[d * 65 + tx * 4 + 3];
            s[0][0] += a0 * c0; s[0][1] += a0 * c1; s[0][2] += a0 * c2; s[0][3] += a0 * c3;
            s[1][0] += a1 * c0; s[1][1] += a1 * c1; s[1][2] += a1 * c2; s[1][3] += a1 * c3;
            s[2][0] += a2 * c0; s[2][1] += a2 * c1; s[2][2] += a2 * c2; s[2][3] += a2 * c3;
            s[3][0] += a3 * c0; s[3][1] += a3 * c1; s[3][2] += a3 * c2; s[3][3] += a3 * c3;
        }

        // masking: attention_mask OR padding -> -1e8 (finite, matches reference),
        // structural k >= TK -> -inf
        const bool chunk_valid = (k0 + tx * 4) < TK_;
#pragma unroll
        for (int i = 0; i < 4; i++) {
            const int q = q0 + ty * 4 + i;
            if (q >= TQ_) {
#pragma unroll
                for (int j = 0; j < 4; j++) s[i][j] = NEGINF_;
                continue;
            }
            unsigned char mv[4] = {0, 0, 0, 0};
            if (chunk_valid) {
                uchar4 mk = *(const uchar4*)&g_mask[(size_t)q * TK_ + k0 + tx * 4];
                mv[0] = mk.x; mv[1] = mk.y; mv[2] = mk.z; mv[3] = mk.w;
            }
#pragma unroll
            for (int j = 0; j < 4; j++) {
                const int k = k0 + tx * 4 + j;
                if (k >= TK_)                s[i][j] = neg_inf_f();
                else if (mv[j] || k >= klen) s[i][j] = NEGINF_;
            }
        }

        // online softmax update (row = q, reduced across the 16 tx lanes)
#pragma unroll
        for (int i = 0; i < 4; i++) {
            float mi = fmaxf(fmaxf(s[i][0], s[i][1]), fmaxf(s[i][2], s[i][3]));
#pragma unroll
            for (int off = 1; off < 16; off <<= 1)
                mi = fmaxf(mi, __shfl_xor_sync(0xffffffffu, mi, off));
            const float mn    = fmaxf(mrow[i], mi);
            const float alpha = __expf(mrow[i] - mn);
            float su = 0.f;
#pragma unroll
            for (int j = 0; j < 4; j++) {
                s[i][j] = __expf(s[i][j] - mn);
                su += s[i][j];
            }
#pragma unroll
            for (int off = 1; off < 16; off <<= 1)
                su += __shfl_xor_sync(0xffffffffu, su, off);
            lrow[i] = lrow[i] * alpha + su;
            mrow[i] = mn;
#pragma unroll
            for (int j = 0; j < 4; j++) o[i][j] *= alpha;
        }

        // write P^T into KP (Kt no longer needed)
        __syncthreads();
#pragma unroll
        for (int i = 0; i < 4; i++)
#pragma unroll
            for (int j = 0; j < 4; j++)
                KP[(tx * 4 + j) * 65 + ty * 4 + i] = s[i][j];
        __syncthreads();

        // o += P @ V
#pragma unroll 16
        for (int k = 0; k < 64; k++) {
            float p0 = KP[k * 65 + ty * 4 + 0];
            float p1 = KP[k * 65 + ty * 4 + 1];
            float p2 = KP[k * 65 + ty * 4 + 2];
            float p3 = KP[k * 65 + ty * 4 + 3];
            float4 vv = *(const float4*)&Vs[k * 64 + tx * 4];
            o[0][0] += p0 * vv.x; o[0][1] += p0 * vv.y; o[0][2] += p0 * vv.z; o[0][3] += p0 * vv.w;
            o[1][0] += p1 * vv.x; o[1][1] += p1 * vv.y; o[1][2] += p1 * vv.z; o[1][3] += p1 * vv.w;
            o[2][0] += p2 * vv.x; o[2][1] += p2 * vv.y; o[2][2] += p2 * vv.z; o[2][3] += p2 * vv.w;
            o[3][0] += p3 * vv.x; o[3][1] += p3 * vv.y; o[3][2] += p3 * vv.z; o[3][3] += p3 * vv.w;
        }
    }

    // finalize: attn[t, b, h*64 + dh] = o / l
#pragma unroll
    for (int i = 0; i < 4; i++) {
        const int t = q0 + ty * 4 + i;
        if (t < TQ_) {
            const float inv = 1.f / lrow[i];
            float4 r;
            r.x = o[i][0] * inv; r.y = o[i][1] * inv;
            r.z = o[i][2] * inv; r.w = o[i][3] * inv;
            *(float4*)&g_attn[((size_t)t * BB + b) * DD + h * DHH + tx * 4] = r;
        }
    }
}

// ---------------------------------------------------------------------------
extern "C" void kernel_launch(void* const* d_in, const int* in_sizes, int n_in,
                              void* d_out, int out_size)
{
    const float* utt = (const float*)d_in[0];
    const float* rc  = (const float*)d_in[1];
    const float* smr = (const float*)d_in[2];
    const float* mem = (const float*)d_in[3];
    const float* Wq  = (const float*)d_in[4];
    const float* bq  = (const float*)d_in[5];
    const float* Wkv = (const float*)d_in[6];
    const float* bkv = (const float*)d_in[7];
    const float* Wo  = (const float*)d_in[8];
    const float* bo  = (const float*)d_in[9];
    const int*   len = (const int*)d_in[10];
    const unsigned char* am = (const unsigned char*)d_in[11];
    float* out = (float*)d_out;

    const int attn_smem = (64 * 64 + 64 * 65 + 64 * 64) * (int)sizeof(float);  // 49408
    cudaFuncSetAttribute(attn_kernel, cudaFuncAttributeMaxDynamicSharedMemorySize, attn_smem);

    detect_mask_mode_kernel<<<1, 256>>>(am);
    convert_mask_kernel<<<(TQ_ * TK_ + 255) / 256, 256>>>(am);

    gemm_kernel<0><<<dim3(4, 69), 256>>>(utt, rc, smr, mem, Wq,  bq,  nullptr);
    gemm_kernel<1><<<dim3(8, 69), 256>>>(utt, rc, smr, mem, Wkv, bkv, nullptr);
    attn_kernel<<<dim3(18, 64), 256, attn_smem>>>(len);
    gemm_kernel<2><<<dim3(4, 69), 256>>>(utt, rc, smr, mem, Wo,  bo,  out);
}

// round 4
// speedup vs baseline: 2.0222x; 2.0222x over previous
#include <cuda_runtime.h>
#include <cuda_bf16.h>
#include <cstdint>

#define TT 1024
#define RR 64
#define SS 16
#define MMEM 16
#define BB 8
#define DD 512
#define HH 8
#define DHH 64
#define TQ_ 1104
#define TK_ 1104
#define SCALE_ 0.125f
#define NEGINF_ (-1.0e8f)

typedef __nv_bfloat16 bf16;

// ---------------- scratch (device globals; allocation-free rule) ----------------
__device__ bf16 g_qin_hi [(size_t)TQ_ * BB * DD];
__device__ bf16 g_qin_lo [(size_t)TQ_ * BB * DD];
__device__ bf16 g_kvin_hi[(size_t)TK_ * BB * DD];
__device__ bf16 g_kvin_lo[(size_t)TK_ * BB * DD];
__device__ bf16 g_w_hi[(size_t)2048 * DD];   // Wq | Wkv | Wo rows
__device__ bf16 g_w_lo[(size_t)2048 * DD];
__device__ bf16 g_q_hi[(size_t)TQ_ * BB * DD];
__device__ bf16 g_q_lo[(size_t)TQ_ * BB * DD];
__device__ bf16 g_k_hi[(size_t)TK_ * BB * DD];
__device__ bf16 g_k_lo[(size_t)TK_ * BB * DD];
__device__ bf16 g_v_hi[(size_t)TK_ * BB * DD];
__device__ bf16 g_v_lo[(size_t)TK_ * BB * DD];
__device__ bf16 g_a_hi[(size_t)TQ_ * BB * DD];
__device__ bf16 g_a_lo[(size_t)TQ_ * BB * DD];
__device__ unsigned char g_mask[(size_t)TQ_ * TK_];
__device__ int g_mask_mode;

__device__ __forceinline__ float neg_inf_f() { return __int_as_float(0xff800000); }

// ---------------- low-level helpers (sm_80-era only; no 'a' features) ----------------
__device__ __forceinline__ uint32_t smem_to_u32(const void* p) {
    uint32_t a;
    asm("{ .reg .u64 t; cvta.to.shared.u64 t, %1; cvt.u32.u64 %0, t; }" : "=r"(a) : "l"(p));
    return a;
}
__device__ __forceinline__ void ldmat4(uint32_t r[4], uint32_t addr) {
    asm volatile("ldmatrix.sync.aligned.m8n8.x4.shared.b16 {%0,%1,%2,%3}, [%4];"
                 : "=r"(r[0]), "=r"(r[1]), "=r"(r[2]), "=r"(r[3]) : "r"(addr));
}
__device__ __forceinline__ void ldmat4t(uint32_t r[4], uint32_t addr) {
    asm volatile("ldmatrix.sync.aligned.m8n8.x4.trans.shared.b16 {%0,%1,%2,%3}, [%4];"
                 : "=r"(r[0]), "=r"(r[1]), "=r"(r[2]), "=r"(r[3]) : "r"(addr));
}
__device__ __forceinline__ void mma16816(float d[4], const uint32_t a[4],
                                         uint32_t b0, uint32_t b1) {
    asm volatile("mma.sync.aligned.m16n8k16.row.col.f32.bf16.bf16.f32 "
                 "{%0,%1,%2,%3}, {%4,%5,%6,%7}, {%8,%9}, {%0,%1,%2,%3};"
                 : "+f"(d[0]), "+f"(d[1]), "+f"(d[2]), "+f"(d[3])
                 : "r"(a[0]), "r"(a[1]), "r"(a[2]), "r"(a[3]), "r"(b0), "r"(b1));
}
__device__ __forceinline__ void cp16(uint32_t dst, const void* src, int bytes) {
    asm volatile("cp.async.cg.shared.global [%0], [%1], 16, %2;"
                 :: "r"(dst), "l"(src), "r"(bytes));
}
#define CP_COMMIT() asm volatile("cp.async.commit_group;" ::: "memory")
#define CP_WAIT0()  asm volatile("cp.async.wait_group 0;" ::: "memory")
#define CP_WAIT1()  asm volatile("cp.async.wait_group 1;" ::: "memory")

#define SWZ(o) ((o) ^ (((o) >> 3) & 0x70))

__device__ __forceinline__ uint32_t pk2(bf16 a, bf16 b) {
    return ((uint32_t)__bfloat16_as_ushort(b) << 16) | __bfloat16_as_ushort(a);
}
__device__ __forceinline__ void split_bf(float x, bf16& h, bf16& l) {
    h = __float2bfloat16(x);
    l = __float2bfloat16(x - __bfloat162float(h));
}
__device__ __forceinline__ uint32_t pk_hi(float a, float b) {
    return pk2(__float2bfloat16(a), __float2bfloat16(b));
}
__device__ __forceinline__ uint32_t pk_lo(float a, float b) {
    bf16 ha = __float2bfloat16(a), hb = __float2bfloat16(b);
    return pk2(__float2bfloat16(a - __bfloat162float(ha)),
               __float2bfloat16(b - __bfloat162float(hb)));
}

// ---------------- mask dtype detect + canonicalize ----------------
__global__ void detect_mask_mode_kernel(const unsigned char* __restrict__ buf)
{
    __shared__ int s_large, s_nzoff;
    if (threadIdx.x == 0) { s_large = 0; s_nzoff = 0; }
    __syncthreads();
    const int N = 1 << 18;
    int l = 0, z = 0;
    for (int i = threadIdx.x; i < N; i += blockDim.x) {
        unsigned char v = buf[i];
        if (v > 1) l = 1;
        if ((i & 3) && v != 0) z = 1;
    }
    if (l) atomicOr(&s_large, 1);
    if (z) atomicOr(&s_nzoff, 1);
    __syncthreads();
    if (threadIdx.x == 0) g_mask_mode = s_large ? 2 : (s_nzoff ? 0 : 1);
}
__global__ void convert_mask_kernel(const unsigned char* __restrict__ buf)
{
    const int idx = blockIdx.x * blockDim.x + threadIdx.x;
    if (idx >= TQ_ * TK_) return;
    const int mode = g_mask_mode;
    unsigned char m;
    if (mode == 0)      m = buf[idx] ? 1 : 0;
    else if (mode == 1) m = (((const int*)buf)[idx] != 0) ? 1 : 0;
    else                m = (((const float*)buf)[idx] != 0.f) ? 1 : 0;
    g_mask[idx] = m;
}

// ---------------- prepass: fp32 -> split bf16 ----------------
__global__ void __launch_bounds__(256) convert_in_kernel(
    const float* __restrict__ utt, const float* __restrict__ rc,
    const float* __restrict__ smr, const float* __restrict__ mem)
{
    const size_t e = ((size_t)blockIdx.x * blockDim.x + threadIdx.x) * 4;
    if (e >= (size_t)TQ_ * BB * DD) return;
    const int r = (int)(e >> 9);
    const int k = (int)(e & 511);
    const int t = r >> 3, b = r & 7;
    const float* src;
    if (blockIdx.y == 0) {
        if (t < RR)           src = rc  + ((size_t)t * BB + b) * DD;
        else if (t < RR + TT) src = utt + ((size_t)(t - RR) * BB + b) * DD;
        else                  src = smr + ((size_t)(t - RR - TT) * BB + b) * DD;
    } else {
        if (t < MMEM)           src = mem + ((size_t)t * BB + b) * DD;
        else if (t < MMEM + RR) src = rc  + ((size_t)(t - MMEM) * BB + b) * DD;
        else                    src = utt + ((size_t)(t - MMEM - RR) * BB + b) * DD;
    }
    float4 v = *(const float4*)(src + k);
    bf16* dh = blockIdx.y ? g_kvin_hi : g_qin_hi;
    bf16* dl = blockIdx.y ? g_kvin_lo : g_qin_lo;
    *(uint2*)&dh[e] = make_uint2(pk_hi(v.x, v.y), pk_hi(v.z, v.w));
    *(uint2*)&dl[e] = make_uint2(pk_lo(v.x, v.y), pk_lo(v.z, v.w));
}

__global__ void __launch_bounds__(256) convert_w_kernel(
    const float* __restrict__ Wq, const float* __restrict__ Wkv, const float* __restrict__ Wo)
{
    const size_t e = ((size_t)blockIdx.x * blockDim.x + threadIdx.x) * 4;
    if (e >= (size_t)2048 * DD) return;
    const int r = (int)(e >> 9);
    const int k = (int)(e & 511);
    const float* src;
    if (r < 512)       src = Wq  + (size_t)r * DD;
    else if (r < 1536) src = Wkv + (size_t)(r - 512) * DD;
    else               src = Wo  + (size_t)(r - 1536) * DD;
    float4 v = *(const float4*)(src + k);
    *(uint2*)&g_w_hi[e] = make_uint2(pk_hi(v.x, v.y), pk_hi(v.z, v.w));
    *(uint2*)&g_w_lo[e] = make_uint2(pk_lo(v.x, v.y), pk_lo(v.z, v.w));
}

// ---------------------------------------------------------------------------
// HMMA split-bf16 GEMM: D[64m x 64n] = A[m,k]*B[n,k]^T + bias, K=512.
// 128 threads / 4 warps (2x2), warp tile 32m x 32n, k-step 16 (m16n8k16),
// 3-MMA split (hh + hl + lh). cp.async double-buffered stages of K=64.
// MODE 0: -> g_q_hi/lo * SCALE    MODE 1: -> g_k/g_v split at n=512
// MODE 2: -> d_out (fp32) with right_context / clipped-mems packing
// dyn smem = 2 stages * 4 tiles * 8KB = 64KB.
// ---------------------------------------------------------------------------
template <int MODE>
__global__ void __launch_bounds__(128) tc_gemm(
    const bf16* __restrict__ a_hi, const bf16* __restrict__ a_lo,
    const bf16* __restrict__ b_hi, const bf16* __restrict__ b_lo,
    const float* __restrict__ bias, float* __restrict__ dout)
{
    extern __shared__ char smc[];
    const uint32_t smb = smem_to_u32(smc);
    const int tid = threadIdx.x, w = tid >> 5, lane = tid & 31;
    const int wm = w >> 1, wn = w & 1;
    const int m0 = blockIdx.y * 64, n0 = blockIdx.x * 64;

    const bf16* srcs[4] = { a_hi + (size_t)m0 * DD, a_lo + (size_t)m0 * DD,
                            b_hi + (size_t)n0 * DD, b_lo + (size_t)n0 * DD };
    const int ldrow = tid >> 1;          // 0..63
    const int ldc0  = (tid & 1) * 4;     // 16B segment base

    auto issue_stage = [&](int kc, int buf) {
#pragma unroll
        for (int t = 0; t < 4; t++) {
            const bf16* src = srcs[t] + (size_t)ldrow * DD + kc * 64 + ldc0 * 8;
            uint32_t db = smb + buf * 32768 + t * 8192;
#pragma unroll
            for (int i = 0; i < 4; i++)
                cp16(db + SWZ((uint32_t)(ldrow * 128 + (ldc0 + i) * 16)), src + i * 8, 16);
        }
        CP_COMMIT();
    };

    float acc[2][4][4];
#pragma unroll
    for (int a = 0; a < 2; a++)
#pragma unroll
        for (int c = 0; c < 4; c++)
#pragma unroll
            for (int d = 0; d < 4; d++) acc[a][c][d] = 0.f;

    const int rr  = (lane & 7) + ((lane >> 3) & 1) * 8;
    const int kk8 = (lane >> 4) * 8;

    issue_stage(0, 0);
    for (int c = 0; c < 8; c++) {
        if (c < 7) { issue_stage(c + 1, (c + 1) & 1); CP_WAIT1(); }
        else       { CP_WAIT0(); }
        __syncthreads();
        const uint32_t base = smb + (c & 1) * 32768;
#pragma unroll
        for (int kd = 0; kd < 4; kd++) {
            const uint32_t ko = (uint32_t)((kd * 16 + kk8) * 2);
            uint32_t ah[2][4], al[2][4], bh[2][4], bl[2][4];
#pragma unroll
            for (int mt = 0; mt < 2; mt++) {
                uint32_t off = SWZ((uint32_t)((wm * 32 + mt * 16 + rr) * 128) + ko);
                ldmat4(ah[mt], base + off);
                ldmat4(al[mt], base + 8192 + off);
            }
#pragma unroll
            for (int p = 0; p < 2; p++) {
                uint32_t off = SWZ((uint32_t)((wn * 32 + p * 16 + rr) * 128) + ko);
                ldmat4(bh[p], base + 16384 + off);
                ldmat4(bl[p], base + 24576 + off);
            }
#pragma unroll
            for (int mt = 0; mt < 2; mt++)
#pragma unroll
                for (int nt = 0; nt < 4; nt++) {
                    uint32_t b0h = bh[nt >> 1][nt & 1], b1h = bh[nt >> 1][2 + (nt & 1)];
                    uint32_t b0l = bl[nt >> 1][nt & 1], b1l = bl[nt >> 1][2 + (nt & 1)];
                    mma16816(acc[mt][nt], ah[mt], b0h, b1h);
                    mma16816(acc[mt][nt], ah[mt], b0l, b1l);
                    mma16816(acc[mt][nt], al[mt], b0h, b1h);
                }
        }
        __syncthreads();
    }

    // epilogue
    const int lq = lane >> 2, lc = (lane & 3) * 2;
#pragma unroll
    for (int mt = 0; mt < 2; mt++) {
#pragma unroll
        for (int nt = 0; nt < 4; nt++) {
            const int col = n0 + wn * 32 + nt * 8 + lc;
            const float b0 = bias[col], b1 = bias[col + 1];
#pragma unroll
            for (int hrow = 0; hrow < 2; hrow++) {
                const int m = m0 + wm * 32 + mt * 16 + lq + hrow * 8;
                float v0 = acc[mt][nt][hrow * 2 + 0] + b0;
                float v1 = acc[mt][nt][hrow * 2 + 1] + b1;
                if (MODE == 0) {
                    v0 *= SCALE_; v1 *= SCALE_;
                    *(uint32_t*)&g_q_hi[(size_t)m * DD + col] = pk_hi(v0, v1);
                    *(uint32_t*)&g_q_lo[(size_t)m * DD + col] = pk_lo(v0, v1);
                } else if (MODE == 1) {
                    if (col < DD) {
                        *(uint32_t*)&g_k_hi[(size_t)m * DD + col] = pk_hi(v0, v1);
                        *(uint32_t*)&g_k_lo[(size_t)m * DD + col] = pk_lo(v0, v1);
                    } else {
                        *(uint32_t*)&g_v_hi[(size_t)m * DD + col - DD] = pk_hi(v0, v1);
                        *(uint32_t*)&g_v_lo[(size_t)m * DD + col - DD] = pk_lo(v0, v1);
                    }
                } else {
                    const int tt = m >> 3, rb = m & 7;
                    if (tt < TQ_ - SS) {
                        *(float2*)&dout[(size_t)m * DD + col] = make_float2(v0, v1);
                    } else if (tt < TQ_ - 1) {
                        v0 = fminf(10.f, fmaxf(-10.f, v0));
                        v1 = fminf(10.f, fmaxf(-10.f, v1));
                        *(float2*)&dout[(size_t)(TQ_ - SS) * BB * DD +
                                        ((size_t)(tt - (TQ_ - SS)) * BB + rb) * DD + col] =
                            make_float2(v0, v1);
                    }
                }
            }
        }
    }
}

// ---------------------------------------------------------------------------
// HMMA flash attention: one CTA per (q-tile 64, b, h). 128 threads / 4 warps,
// warp owns 16 q rows. S = Q K^T via split-bf16 3-MMA; online softmax in
// registers (quad shuffles); P stays in registers as the A-fragment of PV
// (accumulator layout == A layout); V via ldmatrix.trans, split 3-MMA.
// smem: Qhi Qlo Khi Klo Vhi Vlo  = 6 * 8KB = 48KB.
// ---------------------------------------------------------------------------
__global__ void __launch_bounds__(128) attn_kernel(const int* __restrict__ lengths)
{
    extern __shared__ char smc[];
    const uint32_t smb = smem_to_u32(smc);
    const uint32_t Qh = smb, Ql = smb + 8192, Kh = smb + 16384, Kl = smb + 24576;
    const uint32_t Vh = smb + 32768, Vl = smb + 40960;

    const int tid = threadIdx.x, w = tid >> 5, lane = tid & 31;
    const int b = blockIdx.y >> 3, h = blockIdx.y & 7;
    const int q0 = blockIdx.x * 64;

    int maxlen = 0;
#pragma unroll
    for (int i = 0; i < BB; i++) maxlen = max(maxlen, lengths[i]);
    const int klen = lengths[b] + MMEM + (TQ_ - maxlen - SS);
    const int kend = min(TK_, (klen + 63) & ~63);

    const int ldrow = tid >> 1;
    const int ldc0  = (tid & 1) * 4;

    // stage Q (hi/lo), zero-fill rows >= TQ_
    {
        const int q = q0 + ldrow;
        const int bytes = (q < TQ_) ? 16 : 0;
        const size_t go = ((size_t)q * BB + b) * DD + h * DHH + ldc0 * 8;
#pragma unroll
        for (int i = 0; i < 4; i++) {
            uint32_t so = SWZ((uint32_t)(ldrow * 128 + (ldc0 + i) * 16));
            cp16(Qh + so, g_q_hi + go + i * 8, bytes);
            cp16(Ql + so, g_q_lo + go + i * 8, bytes);
        }
        CP_COMMIT(); CP_WAIT0();
    }
    __syncthreads();

    const int rr  = (lane & 7) + ((lane >> 3) & 1) * 8;
    const int kk8 = (lane >> 4) * 8;

    uint32_t qh[4][4], ql[4][4];
#pragma unroll
    for (int kd = 0; kd < 4; kd++) {
        uint32_t off = SWZ((uint32_t)((16 * w + rr) * 128 + (kd * 16 + kk8) * 2));
        ldmat4(qh[kd], Qh + off);
        ldmat4(ql[kd], Ql + off);
    }

    float o[8][4];
#pragma unroll
    for (int j = 0; j < 8; j++)
#pragma unroll
        for (int d = 0; d < 4; d++) o[j][d] = 0.f;
    float mr0 = neg_inf_f(), mr1 = neg_inf_f(), lr0 = 0.f, lr1 = 0.f;

    const int lq = lane >> 2, lc = (lane & 3) * 2;
    const int qr0 = q0 + 16 * w + lq, qr1 = qr0 + 8;

    for (int k0 = 0; k0 < kend; k0 += 64) {
        __syncthreads();   // previous tile's ldmatrix reads complete
        // stage K/V hi+lo, zero-fill rows >= TK_
        {
            const int tk = k0 + ldrow;
            const int bytes = (tk < TK_) ? 16 : 0;
            const size_t go = ((size_t)tk * BB + b) * DD + h * DHH + ldc0 * 8;
#pragma unroll
            for (int i = 0; i < 4; i++) {
                uint32_t so = SWZ((uint32_t)(ldrow * 128 + (ldc0 + i) * 16));
                cp16(Kh + so, g_k_hi + go + i * 8, bytes);
                cp16(Kl + so, g_k_lo + go + i * 8, bytes);
                cp16(Vh + so, g_v_hi + go + i * 8, bytes);
                cp16(Vl + so, g_v_lo + go + i * 8, bytes);
            }
            CP_COMMIT(); CP_WAIT0();
        }
        __syncthreads();

        // ---- S = Q K^T ----
        float s[8][4];
#pragma unroll
        for (int j = 0; j < 8; j++)
#pragma unroll
            for (int d = 0; d < 4; d++) s[j][d] = 0.f;

#pragma unroll
        for (int kd = 0; kd < 4; kd++) {
            const uint32_t ko = (uint32_t)((kd * 16 + kk8) * 2);
#pragma unroll
            for (int p = 0; p < 4; p++) {
                uint32_t kh4[4], kl4[4];
                uint32_t off = SWZ((uint32_t)((p * 16 + rr) * 128) + ko);
                ldmat4(kh4, Kh + off);
                ldmat4(kl4, Kl + off);
                mma16816(s[2 * p],     qh[kd], kh4[0], kh4[2]);
                mma16816(s[2 * p],     qh[kd], kl4[0], kl4[2]);
                mma16816(s[2 * p],     ql[kd], kh4[0], kh4[2]);
                mma16816(s[2 * p + 1], qh[kd], kh4[1], kh4[3]);
                mma16816(s[2 * p + 1], qh[kd], kl4[1], kl4[3]);
                mma16816(s[2 * p + 1], ql[kd], kh4[1], kh4[3]);
            }
        }

        // ---- mask ----
#pragma unroll
        for (int j = 0; j < 8; j++) {
            const int kc = k0 + 8 * j + lc;
            const bool in_k = (kc < TK_ - 1);   // kc is even; pair fits iff kc <= 1102
            uchar2 mA = make_uchar2(1, 1), mB = make_uchar2(1, 1);
            if (in_k && qr0 < TQ_) mA = *(const uchar2*)&g_mask[(size_t)qr0 * TK_ + kc];
            if (in_k && qr1 < TQ_) mB = *(const uchar2*)&g_mask[(size_t)qr1 * TK_ + kc];
            if (mA.x || kc >= klen)     s[j][0] = NEGINF_;
            if (mA.y || kc + 1 >= klen) s[j][1] = NEGINF_;
            if (mB.x || kc >= klen)     s[j][2] = NEGINF_;
            if (mB.y || kc + 1 >= klen) s[j][3] = NEGINF_;
        }

        // ---- online softmax (rows qr0, qr1; reduce across quad lanes) ----
        float mx0 = NEGINF_, mx1 = NEGINF_;
#pragma unroll
        for (int j = 0; j < 8; j++) {
            mx0 = fmaxf(mx0, fmaxf(s[j][0], s[j][1]));
            mx1 = fmaxf(mx1, fmaxf(s[j][2], s[j][3]));
        }
        mx0 = fmaxf(mx0, __shfl_xor_sync(0xffffffffu, mx0, 1));
        mx0 = fmaxf(mx0, __shfl_xor_sync(0xffffffffu, mx0, 2));
        mx1 = fmaxf(mx1, __shfl_xor_sync(0xffffffffu, mx1, 1));
        mx1 = fmaxf(mx1, __shfl_xor_sync(0xffffffffu, mx1, 2));
        const float mn0 = fmaxf(mr0, mx0), mn1 = fmaxf(mr1, mx1);
        const float a0 = __expf(mr0 - mn0), a1 = __expf(mr1 - mn1);
        float su0 = 0.f, su1 = 0.f;
#pragma unroll
        for (int j = 0; j < 8; j++) {
            s[j][0] = __expf(s[j][0] - mn0);
            s[j][1] = __expf(s[j][1] - mn0);
            s[j][2] = __expf(s[j][2] - mn1);
            s[j][3] = __expf(s[j][3] - mn1);
            su0 += s[j][0] + s[j][1];
            su1 += s[j][2] + s[j][3];
        }
        su0 += __shfl_xor_sync(0xffffffffu, su0, 1);
        su0 += __shfl_xor_sync(0xffffffffu, su0, 2);
        su1 += __shfl_xor_sync(0xffffffffu, su1, 1);
        su1 += __shfl_xor_sync(0xffffffffu, su1, 2);
        lr0 = lr0 * a0 + su0;  mr0 = mn0;
        lr1 = lr1 * a1 + su1;  mr1 = mn1;
#pragma unroll
        for (int j = 0; j < 8; j++) {
            o[j][0] *= a0; o[j][1] *= a0;
            o[j][2] *= a1; o[j][3] *= a1;
        }

        // ---- P -> bf16 hi/lo packed (accumulator layout == A-fragment layout) ----
        uint32_t ph0[8], pl0[8], ph1[8], pl1[8];
#pragma unroll
        for (int j = 0; j < 8; j++) {
            ph0[j] = pk_hi(s[j][0], s[j][1]);
            pl0[j] = pk_lo(s[j][0], s[j][1]);
            ph1[j] = pk_hi(s[j][2], s[j][3]);
            pl1[j] = pk_lo(s[j][2], s[j][3]);
        }

        // ---- O += P V ----
#pragma unroll
        for (int kd = 0; kd < 4; kd++) {
            const uint32_t pah[4] = {ph0[2 * kd], ph1[2 * kd], ph0[2 * kd + 1], ph1[2 * kd + 1]};
            const uint32_t pal[4] = {pl0[2 * kd], pl1[2 * kd], pl0[2 * kd + 1], pl1[2 * kd + 1]};
#pragma unroll
            for (int p = 0; p < 4; p++) {
                uint32_t vh4[4], vl4[4];
                uint32_t off = SWZ((uint32_t)((kd * 16 + rr) * 128 + (p * 16 + kk8) * 2));
                ldmat4t(vh4, Vh + off);
                ldmat4t(vl4, Vl + off);
                mma16816(o[2 * p],     pah, vh4[0], vh4[1]);
                mma16816(o[2 * p],     pah, vl4[0], vl4[1]);
                mma16816(o[2 * p],     pal, vh4[0], vh4[1]);
                mma16816(o[2 * p + 1], pah, vh4[2], vh4[3]);
                mma16816(o[2 * p + 1], pah, vl4[2], vl4[3]);
                mma16816(o[2 * p + 1], pal, vh4[2], vh4[3]);
            }
        }
    }

    // ---- epilogue: o / l -> split bf16 for the O projection ----
    const float inv0 = 1.f / lr0, inv1 = 1.f / lr1;
#pragma unroll
    for (int j = 0; j < 8; j++) {
        const int dh = h * DHH + 8 * j + lc;
        if (qr0 < TQ_) {
            const float v0 = o[j][0] * inv0, v1 = o[j][1] * inv0;
            const size_t ad = ((size_t)qr0 * BB + b) * DD + dh;
            *(uint32_t*)&g_a_hi[ad] = pk_hi(v0, v1);
            *(uint32_t*)&g_a_lo[ad] = pk_lo(v0, v1);
        }
        if (qr1 < TQ_) {
            const float v0 = o[j][2] * inv1, v1 = o[j][3] * inv1;
            const size_t ad = ((size_t)qr1 * BB + b) * DD + dh;
            *(uint32_t*)&g_a_hi[ad] = pk_hi(v0, v1);
            *(uint32_t*)&g_a_lo[ad] = pk_lo(v0, v1);
        }
    }
}

// ---------------------------------------------------------------------------
extern "C" void kernel_launch(void* const* d_in, const int* in_sizes, int n_in,
                              void* d_out, int out_size)
{
    const float* utt = (const float*)d_in[0];
    const float* rc  = (const float*)d_in[1];
    const float* smr = (const float*)d_in[2];
    const float* mem = (const float*)d_in[3];
    const float* Wq  = (const float*)d_in[4];
    const float* bq  = (const float*)d_in[5];
    const float* Wkv = (const float*)d_in[6];
    const float* bkv = (const float*)d_in[7];
    const float* Wo  = (const float*)d_in[8];
    const float* bo  = (const float*)d_in[9];
    const int*   len = (const int*)d_in[10];
    const unsigned char* am = (const unsigned char*)d_in[11];
    float* out = (float*)d_out;

    const int gemm_smem = 65536;
    const int attn_smem = 49152;
    cudaFuncSetAttribute(tc_gemm<0>, cudaFuncAttributeMaxDynamicSharedMemorySize, gemm_smem);
    cudaFuncSetAttribute(tc_gemm<1>, cudaFuncAttributeMaxDynamicSharedMemorySize, gemm_smem);
    cudaFuncSetAttribute(tc_gemm<2>, cudaFuncAttributeMaxDynamicSharedMemorySize, gemm_smem);
    cudaFuncSetAttribute(attn_kernel, cudaFuncAttributeMaxDynamicSharedMemorySize, attn_smem);

    detect_mask_mode_kernel<<<1, 256>>>(am);
    convert_mask_kernel<<<(TQ_ * TK_ + 255) / 256, 256>>>(am);
    convert_in_kernel<<<dim3((TQ_ * BB * DD / 4 + 255) / 256, 2), 256>>>(utt, rc, smr, mem);
    convert_w_kernel<<<(2048 * DD / 4 + 255) / 256, 256>>>(Wq, Wkv, Wo);

    bf16 *qinh, *qinl, *kvinh, *kvinl, *ah, *al, *wh, *wl;
    cudaGetSymbolAddress((void**)&qinh,  g_qin_hi);
    cudaGetSymbolAddress((void**)&qinl,  g_qin_lo);
    cudaGetSymbolAddress((void**)&kvinh, g_kvin_hi);
    cudaGetSymbolAddress((void**)&kvinl, g_kvin_lo);
    cudaGetSymbolAddress((void**)&ah,    g_a_hi);
    cudaGetSymbolAddress((void**)&al,    g_a_lo);
    cudaGetSymbolAddress((void**)&wh,    g_w_hi);
    cudaGetSymbolAddress((void**)&wl,    g_w_lo);

    // 8832 = 138 * 64
    tc_gemm<0><<<dim3(8, 138), 128, gemm_smem>>>(qinh, qinl, wh, wl, bq, nullptr);
    tc_gemm<1><<<dim3(16, 138), 128, gemm_smem>>>(kvinh, kvinl, wh + (size_t)512 * DD,
                                                  wl + (size_t)512 * DD, bkv, nullptr);
    attn_kernel<<<dim3(18, 64), 128, attn_smem>>>(len);
    tc_gemm<2><<<dim3(8, 138), 128, gemm_smem>>>(ah, al, wh + (size_t)1536 * DD,
                                                 wl + (size_t)1536 * DD, bo, out);
}